// round 8
// baseline (speedup 1.0000x reference)
#include <cuda_runtime.h>
#include <cuda_bf16.h>
#include <cstdint>
#include <stdint.h>
#include <math.h>

// Problem constants
#define BB   64
#define NN   1025
#define DD   1024
#define CC   64
#define NB   (BB*NN)          // 65600 rows
#define LN_EPS 1e-5f

// Scratch (device globals: allocation-free)
__device__ float g_y[(size_t)NB*CC];            // after GEMM1 (fp32, conv input)
__device__ __nv_bfloat16 g_z[(size_t)NB*CC];    // after conv+gelu (bf16, GEMM2 A)
__device__ __nv_bfloat16 g_w1a[(size_t)DD*CC];  // (ln_w*gamma) ⊙ w1, bf16
__device__ __nv_bfloat16 g_w1b[(size_t)DD*CC];  // gammax ⊙ w1, bf16
__device__ float g_S1p[16][CC];                 // partial col-sums of sc1*w1
__device__ float g_C3p[16][CC];                 // partial col-sums of sc3*w1

__device__ __forceinline__ float gelu_exact(float v) {
    return v * normcdff(v);
}
__device__ __forceinline__ unsigned smem_u32(const void* p) {
    return (unsigned)__cvta_generic_to_shared(p);
}
__device__ __forceinline__ void ldsm_x4(uint32_t (&r)[4], unsigned addr) {
    asm volatile("ldmatrix.sync.aligned.m8n8.x4.shared.b16 {%0,%1,%2,%3}, [%4];"
        : "=r"(r[0]), "=r"(r[1]), "=r"(r[2]), "=r"(r[3]) : "r"(addr));
}
__device__ __forceinline__ void ldsm_x2t(uint32_t (&r)[2], unsigned addr) {
    asm volatile("ldmatrix.sync.aligned.m8n8.x2.trans.shared.b16 {%0,%1}, [%2];"
        : "=r"(r[0]), "=r"(r[1]) : "r"(addr));
}
__device__ __forceinline__ void mma_bf16(float (&d)[4], const uint32_t (&a)[4],
                                         const uint32_t (&b)[2]) {
    asm volatile("mma.sync.aligned.m16n8k16.row.col.f32.bf16.bf16.f32 "
        "{%0,%1,%2,%3}, {%4,%5,%6,%7}, {%8,%9}, {%0,%1,%2,%3};"
        : "+f"(d[0]), "+f"(d[1]), "+f"(d[2]), "+f"(d[3])
        : "r"(a[0]), "r"(a[1]), "r"(a[2]), "r"(a[3]), "r"(b[0]), "r"(b[1]));
}
__device__ __forceinline__ void cp_async16(unsigned saddr, const void* gptr) {
    asm volatile("cp.async.cg.shared.global [%0], [%1], 16;" :: "r"(saddr), "l"(gptr));
}
__device__ __forceinline__ void cp_commit() {
    asm volatile("cp.async.commit_group;");
}
__device__ __forceinline__ void cp_wait0() {
    asm volatile("cp.async.wait_group 0;");
}

// ---------------------------------------------------------------------------
// Kernel 0: prep. Bake LN scales into w1 (bf16) + partial column sums.
// ---------------------------------------------------------------------------
__global__ __launch_bounds__(256) void k_prep(
    const float* __restrict__ ln_w, const float* __restrict__ ln_b,
    const float* __restrict__ gamma, const float* __restrict__ gammax,
    const float* __restrict__ w1)
{
    __shared__ float redS[4][CC];
    __shared__ float redC[4][CC];
    int tid = threadIdx.x;
    int k0 = blockIdx.x * 64;
    int c = tid & 63;
    int kg = tid >> 6;
    float s1p = 0.f, c3p = 0.f;
#pragma unroll
    for (int i = 0; i < 16; i++) {
        int kk = kg + 4 * i;
        int k = k0 + kk;
        float w = w1[(size_t)k * CC + c];
        float g = gamma[k];
        float sc1 = ln_w[k] * g;
        float sc3 = ln_b[k] * g;
        float sc2 = gammax[k];
        g_w1a[(size_t)k * CC + c] = __float2bfloat16(sc1 * w);
        g_w1b[(size_t)k * CC + c] = __float2bfloat16(sc2 * w);
        s1p += sc1 * w;
        c3p += sc3 * w;
    }
    redS[kg][c] = s1p;
    redC[kg][c] = c3p;
    __syncthreads();
    if (tid < 64) {
        g_S1p[blockIdx.x][tid] = redS[0][tid] + redS[1][tid] + redS[2][tid] + redS[3][tid];
        g_C3p[blockIdx.x][tid] = redC[0][tid] + redC[1][tid] + redC[2][tid] + redC[3][tid];
    }
}

// ---------------------------------------------------------------------------
// Kernel 1: fused LN-stats + decomposed GEMM1 with cp.async 2-stage pipeline.
// ---------------------------------------------------------------------------
#define F1_SA 72
#define F1_SB 72
#define F1_ST 68
#define F1_STAGE_SZ (128 * F1_ST)
#define F1_SMEM (2*F1_STAGE_SZ*4 + 128*F1_SA*2 + 64*F1_SB*2*2 + 2*CC*4 + 2*128*4 + 128*4)

__global__ __launch_bounds__(256, 2) void k_fused1(
    const float* __restrict__ x, const float* __restrict__ b1)
{
    extern __shared__ char fsm[];
    float* stage = (float*)fsm;
    __nv_bfloat16* sA  = (__nv_bfloat16*)(fsm + 2*F1_STAGE_SZ*4);
    __nv_bfloat16* sB1 = sA + 128 * F1_SA;
    __nv_bfloat16* sB2 = sB1 + 64 * F1_SB;
    float* sS1 = (float*)(sB2 + 64 * F1_SB);
    float* sC3 = sS1 + CC;
    float* smu = sC3 + CC;
    float* srs = smu + 128;
    int*   soff = (int*)(srs + 128);

    int tid = threadIdx.x;
    int lane = tid & 31, wid = tid >> 5;
    int warp_m = wid >> 1, warp_n = wid & 1;
    int r0 = blockIdx.x * 128;

    if (tid < 64) {
        float s1 = 0.f, c3 = 0.f;
#pragma unroll
        for (int p = 0; p < 16; p++) { s1 += g_S1p[p][tid]; c3 += g_C3p[p][tid]; }
        sS1[tid] = s1;
        sC3[tid] = c3;
    }
    if (tid < 128) {
        int r = r0 + tid;
        int rr = (r < NB) ? r : 0;
        int b = rr / NN;
        int n = rr - b * NN;
        soff[tid] = (n * BB + b) * DD;
    }
    __syncthreads();

    int rowA = tid >> 4;
    int kqA = (tid & 15) * 4;

#pragma unroll
    for (int i = 0; i < 8; i++) {
        int row = rowA + 16 * i;
        cp_async16(smem_u32(&stage[row * F1_ST + kqA]),
                   x + soff[row] + kqA);
    }
    cp_commit();

    float acc1[2][4][4] = {};
    float acc2[2][4][4] = {};
    float sumx[8] = {}, sumxx[8] = {};

    unsigned aAddr0 = smem_u32(&sA[(warp_m * 32 + (lane & 15)) * F1_SA + (lane >> 4) * 8]);
    unsigned b1Addr0 = smem_u32(&sB1[(lane & 15) * F1_SB + warp_n * 32]);
    unsigned b2Addr0 = smem_u32(&sB2[(lane & 15) * F1_SB + warp_n * 32]);

    int pc = 0;
    for (int kc = 0; kc < DD; kc += 64, pc ^= 1) {
        cp_wait0();
        __syncthreads();

        if (kc + 64 < DD) {
#pragma unroll
            for (int i = 0; i < 8; i++) {
                int row = rowA + 16 * i;
                cp_async16(smem_u32(&stage[(pc ^ 1) * F1_STAGE_SZ + row * F1_ST + kqA]),
                           x + soff[row] + kc + 64 + kqA);
            }
            cp_commit();
        }

        uint4 br1[2], br2[2];
#pragma unroll
        for (int i = 0; i < 2; i++) {
            int s = tid + i * 256;
            int kk = s >> 3;
            int q = (s & 7) * 8;
            br1[i] = *(const uint4*)(g_w1a + (size_t)(kc + kk) * CC + q);
            br2[i] = *(const uint4*)(g_w1b + (size_t)(kc + kk) * CC + q);
        }

#pragma unroll
        for (int i = 0; i < 8; i++) {
            int row = rowA + 16 * i;
            float4 v = *(const float4*)&stage[pc * F1_STAGE_SZ + row * F1_ST + kqA];
            sumx[i]  += v.x + v.y + v.z + v.w;
            sumxx[i] += v.x * v.x + v.y * v.y + v.z * v.z + v.w * v.w;
            *(__nv_bfloat162*)&sA[row * F1_SA + kqA]     = __floats2bfloat162_rn(v.x, v.y);
            *(__nv_bfloat162*)&sA[row * F1_SA + kqA + 2] = __floats2bfloat162_rn(v.z, v.w);
        }
#pragma unroll
        for (int i = 0; i < 2; i++) {
            int s = tid + i * 256;
            int kk = s >> 3;
            int q = (s & 7) * 8;
            *(uint4*)&sB1[kk * F1_SB + q] = br1[i];
            *(uint4*)&sB2[kk * F1_SB + q] = br2[i];
        }
        __syncthreads();

#pragma unroll
        for (int ks = 0; ks < 4; ks++) {
            uint32_t a[2][4];
            ldsm_x4(a[0], aAddr0 + ks * 32);
            ldsm_x4(a[1], aAddr0 + 16 * F1_SA * 2 + ks * 32);
#pragma unroll
            for (int ni = 0; ni < 4; ni++) {
                uint32_t bb1[2], bb2[2];
                ldsm_x2t(bb1, b1Addr0 + ks * 16 * F1_SB * 2 + ni * 16);
                ldsm_x2t(bb2, b2Addr0 + ks * 16 * F1_SB * 2 + ni * 16);
#pragma unroll
                for (int mi = 0; mi < 2; mi++) {
                    mma_bf16(acc1[mi][ni], a[mi], bb1);
                    mma_bf16(acc2[mi][ni], a[mi], bb2);
                }
            }
        }
    }
    __syncthreads();

#pragma unroll
    for (int i = 0; i < 8; i++) {
#pragma unroll
        for (int o = 8; o; o >>= 1) {
            sumx[i]  += __shfl_xor_sync(0xffffffffu, sumx[i], o);
            sumxx[i] += __shfl_xor_sync(0xffffffffu, sumxx[i], o);
        }
    }
    if ((tid & 15) == 0) {
#pragma unroll
        for (int i = 0; i < 8; i++) {
            int row = rowA + 16 * i;
            float m = sumx[i] * (1.f / DD);
            float var = sumxx[i] * (1.f / DD) - m * m;
            smu[row] = m;
            srs[row] = rsqrtf(var + LN_EPS);
        }
    }
    __syncthreads();

    int row_in = lane >> 2;
    int colq = (lane & 3) * 2;
#pragma unroll
    for (int mi = 0; mi < 2; mi++) {
#pragma unroll
        for (int h = 0; h < 2; h++) {
            int rl = warp_m * 32 + mi * 16 + row_in + h * 8;
            int r = r0 + rl;
            if (r >= NB) continue;
            float mu = smu[rl], rs = srs[rl];
            float mrs = mu * rs;
#pragma unroll
            for (int ni = 0; ni < 4; ni++) {
                int col = warp_n * 32 + ni * 8 + colq;
                float2 bias = *(const float2*)(b1 + col);
                float v0 = rs * acc1[mi][ni][2 * h]     + acc2[mi][ni][2 * h]
                         + sC3[col]     - mrs * sS1[col]     + bias.x;
                float v1 = rs * acc1[mi][ni][2 * h + 1] + acc2[mi][ni][2 * h + 1]
                         + sC3[col + 1] - mrs * sS1[col + 1] + bias.y;
                *(float2*)(g_y + (size_t)r * CC + col) = make_float2(v0, v1);
            }
        }
    }
}

// ---------------------------------------------------------------------------
// Kernel 3: multi-scale depthwise conv (collapsed 7x7) + residual + 1x1 proj
//           + residual + exact GELU -> z (bf16). 2-row strips, 2 blocks/SM.
// ---------------------------------------------------------------------------
#define CV_ROWS 8
#define CV_COLS 38
#define CV_STRIDE (CV_COLS * 64)
#define CV_SIN (CV_ROWS * CV_STRIDE)
#define CV_S2  (2 * 32 * 64)
#define CV_PW  (64 * 64)
#define CONV_SMEM ((CV_SIN + CV_S2 + CV_PW) * sizeof(float))

__global__ __launch_bounds__(256, 2) void k_conv(
    const float* __restrict__ dw3_w, const float* __restrict__ dw3_b,
    const float* __restrict__ dw5_w, const float* __restrict__ dw5_b,
    const float* __restrict__ dw7_w, const float* __restrict__ dw7_b,
    const float* __restrict__ proj_w, const float* __restrict__ proj_b)
{
    extern __shared__ float sm[];
    float* sIn = sm;
    float* s2  = sm + CV_SIN;
    float* pws = s2 + CV_S2;

    int tid = threadIdx.x;
    int b = blockIdx.x >> 4;
    int strip = blockIdx.x & 15;
    int i0 = strip * 2;
    const float* yb = g_y + (size_t)b * NN * CC;

    for (int idx = tid; idx < CV_SIN; idx += 256) {
        int rr  = idx / CV_STRIDE;
        int rem = idx - rr * CV_STRIDE;
        int col = rem >> 6;
        int c   = rem & 63;
        int gy = i0 - 3 + rr;
        int gx = col - 3;
        float v = 0.f;
        if (gy >= 0 && gy < 32 && gx >= 0 && gx < 32)
            v = yb[(size_t)(1 + gy * 32 + gx) * CC + c];
        sIn[idx] = v;
    }
    for (int idx = tid; idx < CV_PW; idx += 256) {
        int c = idx >> 6, o = idx & 63;
        pws[idx] = proj_w[(size_t)o * CC + c];
    }

    int c = tid & 63;
    float wreg[49];
    float beff;
    {
        const float* w7 = dw7_w + c * 49;
        const float* w5 = dw5_w + c * 25;
        const float* w3 = dw3_w + c * 9;
#pragma unroll
        for (int dy = 0; dy < 7; dy++)
#pragma unroll
            for (int dx = 0; dx < 7; dx++) {
                float v = w7[dy * 7 + dx];
                if (dy >= 1 && dy <= 5 && dx >= 1 && dx <= 5) v += w5[(dy - 1) * 5 + (dx - 1)];
                if (dy >= 2 && dy <= 4 && dx >= 2 && dx <= 4) v += w3[(dy - 2) * 3 + (dx - 2)];
                wreg[dy * 7 + dx] = v * (1.f / 3.f);
            }
        beff = (dw3_b[c] + dw5_b[c] + dw7_b[c]) * (1.f / 3.f);
    }
    __syncthreads();

    int row = (tid >> 6) & 1;
    int jbase = (tid >> 7) * 16;
#pragma unroll 2
    for (int jj = 0; jj < 16; jj++) {
        int j = jbase + jj;
        float acc = beff;
#pragma unroll
        for (int dy = 0; dy < 7; dy++) {
            const float* rp = sIn + ((row + dy) * CV_COLS + j) * 64 + c;
#pragma unroll
            for (int dx = 0; dx < 7; dx++)
                acc += rp[dx * 64] * wreg[dy * 7 + dx];
        }
        float center = sIn[((row + 3) * CV_COLS + (j + 3)) * 64 + c];
        s2[(row * 32 + j) * 64 + c] = acc + center;
    }
    __syncthreads();

    int og = tid & 15, pg = tid >> 4;
    int o0 = og * 4, px0 = pg * 4;
    float pacc[4][4] = {};
    for (int cc = 0; cc < 64; cc++) {
        float wv[4];
        *(float4*)wv = *(const float4*)&pws[cc * 64 + o0];
#pragma unroll
        for (int i = 0; i < 4; i++) {
            float sv = s2[(px0 + i) * 64 + cc];
#pragma unroll
            for (int j = 0; j < 4; j++) pacc[i][j] += sv * wv[j];
        }
    }
    float pb[4];
    *(float4*)pb = *(const float4*)(proj_b + o0);
#pragma unroll
    for (int i = 0; i < 4; i++) {
        int px = px0 + i;
        size_t zoff = ((size_t)b * NN + 1 + i0 * 32 + px) * CC + o0;
        float v0 = gelu_exact(s2[px * 64 + o0 + 0] + pacc[i][0] + pb[0]);
        float v1 = gelu_exact(s2[px * 64 + o0 + 1] + pacc[i][1] + pb[1]);
        float v2 = gelu_exact(s2[px * 64 + o0 + 2] + pacc[i][2] + pb[2]);
        float v3 = gelu_exact(s2[px * 64 + o0 + 3] + pacc[i][3] + pb[3]);
        *(__nv_bfloat162*)(g_z + zoff)     = __floats2bfloat162_rn(v0, v1);
        *(__nv_bfloat162*)(g_z + zoff + 2) = __floats2bfloat162_rn(v2, v3);
    }

    if (strip == 0 && tid < 64) {
        float v = yb[tid];
        g_z[(size_t)b * NN * CC + tid] = __float2bfloat16(gelu_exact(v));
    }
}

// ---------------------------------------------------------------------------
// Kernel 4: z(bf16) @ w2 + b2 + identity(x) -> out. Tile 128x64, K=64.
// Epilogue staged through smem for fully-coalesced float4 x/out traffic.
// ---------------------------------------------------------------------------
#define G2_SA 72
#define G2_SB 72
#define G2_SO 68     // fp32 out-stage stride
#define G2_SMEM_BYTES (128 * G2_SO * 4)

__global__ __launch_bounds__(256) void k_gemm2(
    const float* __restrict__ w2, const float* __restrict__ b2,
    const float* __restrict__ x, float* __restrict__ out)
{
    __shared__ __align__(16) char g2s[G2_SMEM_BYTES];
    __nv_bfloat16* sA = (__nv_bfloat16*)g2s;          // 128 x 72
    __nv_bfloat16* sB = sA + 128 * G2_SA;             // 64 x 72
    float* sOut = (float*)g2s;                        // 128 x 68 (reuses sA/sB)

    int tid = threadIdx.x, lane = tid & 31, wid = tid >> 5;
    int warp_m = wid >> 1, warp_n = wid & 1;
    int r0 = blockIdx.x * 128;
    int c0 = blockIdx.y * 64;

    // A tile: z bf16, 128 x 64
#pragma unroll
    for (int i = 0; i < 4; i++) {
        int s = tid + i * 256;
        int row = s >> 3;
        int cq = (s & 7) * 8;
        int r = r0 + row;
        uint4 v = make_uint4(0, 0, 0, 0);
        if (r < NB) v = *(const uint4*)(g_z + (size_t)r * CC + cq);
        *(uint4*)&sA[row * G2_SA + cq] = v;
    }
    // B tile: w2[0..63][c0..c0+63] fp32 -> bf16
#pragma unroll
    for (int i = 0; i < 4; i++) {
        int s = tid + i * 256;
        int k = s >> 4;
        int cc = (s & 15) * 4;
        float4 v = *(const float4*)(w2 + (size_t)k * DD + c0 + cc);
        *(__nv_bfloat162*)&sB[k * G2_SB + cc]     = __floats2bfloat162_rn(v.x, v.y);
        *(__nv_bfloat162*)&sB[k * G2_SB + cc + 2] = __floats2bfloat162_rn(v.z, v.w);
    }
    __syncthreads();

    float acc[2][4][4] = {};
    unsigned aAddr0 = smem_u32(&sA[(warp_m * 32 + (lane & 15)) * G2_SA + (lane >> 4) * 8]);
    unsigned bAddr0 = smem_u32(&sB[(lane & 15) * G2_SB + warp_n * 32]);

#pragma unroll
    for (int ks = 0; ks < 4; ks++) {
        uint32_t a[2][4];
        ldsm_x4(a[0], aAddr0 + ks * 32);
        ldsm_x4(a[1], aAddr0 + 16 * G2_SA * 2 + ks * 32);
#pragma unroll
        for (int ni = 0; ni < 4; ni++) {
            uint32_t b[2];
            ldsm_x2t(b, bAddr0 + ks * 16 * G2_SB * 2 + ni * 16);
            mma_bf16(acc[0][ni], a[0], b);
            mma_bf16(acc[1][ni], a[1], b);
        }
    }

    // stage accumulators to smem (sA/sB are dead after this barrier)
    __syncthreads();
    int row_in = lane >> 2, colq = (lane & 3) * 2;
#pragma unroll
    for (int mi = 0; mi < 2; mi++) {
#pragma unroll
        for (int h = 0; h < 2; h++) {
            int rl = warp_m * 32 + mi * 16 + row_in + h * 8;
#pragma unroll
            for (int ni = 0; ni < 4; ni++) {
                int col = warp_n * 32 + ni * 8 + colq;
                *(float2*)&sOut[rl * G2_SO + col] =
                    make_float2(acc[mi][ni][2 * h], acc[mi][ni][2 * h + 1]);
            }
        }
    }
    __syncthreads();

    // coalesced epilogue: 16 lanes sweep one row's 64 floats as float4
#pragma unroll
    for (int i = 0; i < 8; i++) {
        int s = tid + i * 256;
        int row = s >> 4;
        int q = (s & 15) * 4;
        int r = r0 + row;
        if (r >= NB) continue;
        int b = r / NN, n = r - b * NN;
        size_t off = (size_t)(n * BB + b) * DD + c0 + q;
        float4 a = *(const float4*)&sOut[row * G2_SO + q];
        float4 xv = *(const float4*)(x + off);
        float4 bias = *(const float4*)(b2 + c0 + q);
        float4 o;
        o.x = xv.x + a.x + bias.x;
        o.y = xv.y + a.y + bias.y;
        o.z = xv.z + a.z + bias.z;
        o.w = xv.w + a.w + bias.w;
        *(float4*)(out + off) = o;
    }
}

// ---------------------------------------------------------------------------
extern "C" void kernel_launch(void* const* d_in, const int* in_sizes, int n_in,
                              void* d_out, int out_size) {
    const float* x      = (const float*)d_in[0];
    const float* ln_w   = (const float*)d_in[1];
    const float* ln_b   = (const float*)d_in[2];
    const float* gamma  = (const float*)d_in[3];
    const float* gammax = (const float*)d_in[4];
    const float* w1     = (const float*)d_in[5];
    const float* b1     = (const float*)d_in[6];
    const float* w2     = (const float*)d_in[7];
    const float* b2     = (const float*)d_in[8];
    const float* dw3_w  = (const float*)d_in[9];
    const float* dw3_b  = (const float*)d_in[10];
    const float* dw5_w  = (const float*)d_in[11];
    const float* dw5_b  = (const float*)d_in[12];
    const float* dw7_w  = (const float*)d_in[13];
    const float* dw7_b  = (const float*)d_in[14];
    const float* proj_w = (const float*)d_in[15];
    const float* proj_b = (const float*)d_in[16];
    float* out = (float*)d_out;

    cudaFuncSetAttribute(k_fused1, cudaFuncAttributeMaxDynamicSharedMemorySize,
                         (int)F1_SMEM);
    cudaFuncSetAttribute(k_conv, cudaFuncAttributeMaxDynamicSharedMemorySize,
                         (int)CONV_SMEM);

    k_prep<<<16, 256>>>(ln_w, ln_b, gamma, gammax, w1);
    k_fused1<<<(NB + 127) / 128, 256, F1_SMEM>>>(x, b1);
    k_conv<<<BB * 16, 256, CONV_SMEM>>>(dw3_w, dw3_b, dw5_w, dw5_b,
                                        dw7_w, dw7_b, proj_w, proj_b);
    k_gemm2<<<dim3((NB + 127) / 128, DD / 64), 256>>>(w2, b2, x, out);
}